// round 13
// baseline (speedup 1.0000x reference)
#include <cuda_runtime.h>
#include <cuda_bf16.h>
#include <cuda_fp16.h>
#include <cstdint>

#define NN 100000
#define DD 64
#define HH 256
#define EE 1000000
#define TT (2 * NN)              // cursor array: [0,NN) geo, [NN,2NN) trans
#define BCAP 64                  // bucket capacity; deg~Poisson(10), P(>64)~1e-30

// ---------------- scratch (device globals; no allocation allowed) ----------
__device__ __align__(16) float g_geo[NN * DD];     // geo segment sums
__device__ __align__(16) float g_trans[NN * DD];   // trans weighted sums
__device__ __align__(16) __half g_feat16[NN * DD]; // fp16 copy of loc_feat
__device__ int g_cnt[TT];                          // bucket cursors == degrees
__device__ int g_gsrc[NN * BCAP];                  // geo bucket payload: src
__device__ int g_tsrc[NN * BCAP];                  // trans bucket payload: src
__device__ float g_twv[NN * BCAP];                 // trans bucket payload: weight
__device__ float g_w[2];

__device__ __forceinline__ float fast_tanh(float x) {
    float y;
    asm("tanh.approx.f32 %0, %1;" : "=f"(y) : "f"(x));
    return y;
}

// ---------------- zero cursors --------------------------------------------
__global__ void zero_kernel() {
    int i = blockIdx.x * blockDim.x + threadIdx.x;
    int stride = gridDim.x * blockDim.x;
    for (int j = i; j < TT; j += stride) g_cnt[j] = 0;
    if (i < 2) g_w[i] = 0.f;
}

// ---------------- fp32 -> fp16 feature conversion --------------------------
__global__ void convert_kernel(const float4* __restrict__ feat) {
    int i = blockIdx.x * blockDim.x + threadIdx.x;
    const int M = NN * DD / 4;
    if (i >= M) return;
    float4 v = feat[i];
    __half2 h0 = __floats2half2_rn(v.x, v.y);
    __half2 h1 = __floats2half2_rn(v.z, v.w);
    reinterpret_cast<__half2*>(g_feat16)[2 * i] = h0;
    reinterpret_cast<__half2*>(g_feat16)[2 * i + 1] = h1;
}

// ---------------- bucket fill (atomic cursor bump, direct write) -----------
__global__ void fill_kernel(const int* __restrict__ gs, const int* __restrict__ gd,
                            const int* __restrict__ ts, const int* __restrict__ td,
                            const float* __restrict__ tw, int E) {
    int e = blockIdx.x * blockDim.x + threadIdx.x;
    if (e >= E) return;
    int d = gd[e];
    int slot = atomicAdd(&g_cnt[d], 1);
    if (slot < BCAP) g_gsrc[d * BCAP + slot] = gs[e];
    int d2 = td[e];
    int s2 = atomicAdd(&g_cnt[NN + d2], 1);
    if (s2 < BCAP) {
        g_tsrc[d2 * BCAP + s2] = ts[e];
        g_twv[d2 * BCAP + s2] = tw[e];
    }
}

// ---------------- gather: warp per (relation, node), fp16 reads ------------
// lane covers 2 halves (half2, 4B) of the 64-elem row; fp32 accumulate.
__global__ void gather_kernel() {
    int gw = (blockIdx.x * blockDim.x + threadIdx.x) >> 5;
    int lane = threadIdx.x & 31;
    if (gw >= TT) return;
    int rel = gw >= NN;
    int node = gw - rel * NN;
    int cnt = g_cnt[rel * NN + node];
    cnt = cnt < BCAP ? cnt : BCAP;
    int base = node * BCAP;
    const __half2* __restrict__ feat = reinterpret_cast<const __half2*>(g_feat16);
    float2 acc = make_float2(0.f, 0.f);
    if (!rel) {
        const int* __restrict__ sidx = g_gsrc + base;
        int j = 0;
        for (; j + 4 <= cnt; j += 4) {
            int s0 = sidx[j], s1 = sidx[j + 1], s2 = sidx[j + 2], s3 = sidx[j + 3];
            float2 v0 = __half22float2(feat[s0 * 32 + lane]);
            float2 v1 = __half22float2(feat[s1 * 32 + lane]);
            float2 v2 = __half22float2(feat[s2 * 32 + lane]);
            float2 v3 = __half22float2(feat[s3 * 32 + lane]);
            acc.x += (v0.x + v1.x) + (v2.x + v3.x);
            acc.y += (v0.y + v1.y) + (v2.y + v3.y);
        }
        for (; j < cnt; j++) {
            float2 v = __half22float2(feat[sidx[j] * 32 + lane]);
            acc.x += v.x; acc.y += v.y;
        }
        reinterpret_cast<float2*>(g_geo)[node * 32 + lane] = acc;
    } else {
        const int* __restrict__ sidx = g_tsrc + base;
        const float* __restrict__ sw = g_twv + base;
        int j = 0;
        for (; j + 4 <= cnt; j += 4) {
            int s0 = sidx[j], s1 = sidx[j + 1], s2 = sidx[j + 2], s3 = sidx[j + 3];
            float w0 = sw[j], w1 = sw[j + 1], w2 = sw[j + 2], w3 = sw[j + 3];
            float2 v0 = __half22float2(feat[s0 * 32 + lane]);
            float2 v1 = __half22float2(feat[s1 * 32 + lane]);
            float2 v2 = __half22float2(feat[s2 * 32 + lane]);
            float2 v3 = __half22float2(feat[s3 * 32 + lane]);
            acc.x = fmaf(v0.x, w0, acc.x); acc.y = fmaf(v0.y, w0, acc.y);
            acc.x = fmaf(v1.x, w1, acc.x); acc.y = fmaf(v1.y, w1, acc.y);
            acc.x = fmaf(v2.x, w2, acc.x); acc.y = fmaf(v2.y, w2, acc.y);
            acc.x = fmaf(v3.x, w3, acc.x); acc.y = fmaf(v3.y, w3, acc.y);
        }
        for (; j < cnt; j++) {
            float w = sw[j];
            float2 v = __half22float2(feat[sidx[j] * 32 + lane]);
            acc.x = fmaf(v.x, w, acc.x); acc.y = fmaf(v.y, w, acc.y);
        }
        reinterpret_cast<float2*>(g_trans)[node * 32 + lane] = acc;
    }
}

// ---------------- semantic attention via mma.sync (bf16 HMMA) --------------
#define TILE_NODES 64
#define NTILES ((NN + TILE_NODES - 1) / TILE_NODES)   // 1563 (last partial)
#define A_STRIDE 144

#define SM_A      0                        // 128 * 144            = 18432
#define SM_BFRag  18432                    // 8192 u32             = 32768
#define SM_B1     (18432 + 32768)          // 256 f32              = 1024
#define SM_W2     (SM_B1 + 1024)           // 256 f32              = 1024
#define SM_TOTAL  (SM_W2 + 1024)           // 53248

__device__ __forceinline__ void mma16816(float& c0, float& c1, float& c2, float& c3,
                                         uint32_t a0, uint32_t a1, uint32_t a2, uint32_t a3,
                                         uint32_t b0, uint32_t b1) {
    asm volatile(
        "mma.sync.aligned.m16n8k16.row.col.f32.bf16.bf16.f32 "
        "{%0,%1,%2,%3}, {%4,%5,%6,%7}, {%8,%9}, {%0,%1,%2,%3};"
        : "+f"(c0), "+f"(c1), "+f"(c2), "+f"(c3)
        : "r"(a0), "r"(a1), "r"(a2), "r"(a3), "r"(b0), "r"(b1));
}

__global__ __launch_bounds__(256)
void semantic_mma_kernel(const float* __restrict__ W1,
                         const float* __restrict__ b1,
                         const float* __restrict__ W2) {
    extern __shared__ char smem[];
    char* sA = smem + SM_A;
    uint32_t* sBf = reinterpret_cast<uint32_t*>(smem + SM_BFRag);
    float* sB1 = reinterpret_cast<float*>(smem + SM_B1);
    float* sW2 = reinterpret_cast<float*>(smem + SM_W2);
    __shared__ float sred[2];

    int tid = threadIdx.x;
    int lane = tid & 31;
    int wid = tid >> 5;

    for (int idx = tid; idx < 8192; idx += 256) {
        int l = idx & 31;
        int r = (idx >> 5) & 1;
        int ks = (idx >> 6) & 3;
        int nt = idx >> 8;
        int k0 = ks * 16 + 2 * (l & 3) + r * 8;
        int n = nt * 8 + (l >> 2);
        __nv_bfloat162 p = __floats2bfloat162_rn(W1[k0 * 256 + n], W1[(k0 + 1) * 256 + n]);
        sBf[idx] = *reinterpret_cast<uint32_t*>(&p);
    }
    if (tid < 256) { sB1[tid] = b1[tid]; sW2[tid] = W2[tid]; }
    if (tid < 2) sred[tid] = 0.f;

    const int rbase = wid * 16 + (lane >> 2);
    float wacc = 0.f;

    for (int tile = blockIdx.x; tile < NTILES; tile += gridDim.x) {
        __syncthreads();
        for (int q = tid; q < 2048; q += 256) {
            int row = q >> 4, comp = q & 15;
            int node = tile * TILE_NODES + (row >> 1);
            float4 v = make_float4(0.f, 0.f, 0.f, 0.f);
            if (node < NN) {
                if ((row & 1) == 0) {
                    v = reinterpret_cast<const float4*>(g_geo)[node * 16 + comp];
                    int c = g_cnt[node];
                    float inv = c > 0 ? 1.f / (float)c : 0.f;
                    v.x *= inv; v.y *= inv; v.z *= inv; v.w *= inv;
                } else {
                    v = reinterpret_cast<const float4*>(g_trans)[node * 16 + comp];
                }
            }
            __nv_bfloat162 p0 = __floats2bfloat162_rn(v.x, v.y);
            __nv_bfloat162 p1 = __floats2bfloat162_rn(v.z, v.w);
            uint2 pk;
            pk.x = *reinterpret_cast<uint32_t*>(&p0);
            pk.y = *reinterpret_cast<uint32_t*>(&p1);
            *reinterpret_cast<uint2*>(sA + row * A_STRIDE + comp * 8) = pk;
        }
        __syncthreads();

        uint32_t a[4][4];
        {
            int r0 = rbase, r1 = rbase + 8;
            #pragma unroll
            for (int ks = 0; ks < 4; ks++) {
                int kb = (ks * 16 + 2 * (lane & 3)) * 2;
                a[ks][0] = *reinterpret_cast<const uint32_t*>(sA + r0 * A_STRIDE + kb);
                a[ks][1] = *reinterpret_cast<const uint32_t*>(sA + r1 * A_STRIDE + kb);
                a[ks][2] = *reinterpret_cast<const uint32_t*>(sA + r0 * A_STRIDE + kb + 16);
                a[ks][3] = *reinterpret_cast<const uint32_t*>(sA + r1 * A_STRIDE + kb + 16);
            }
        }

        float ts0 = 0.f, ts1 = 0.f;
        #pragma unroll 4
        for (int nt = 0; nt < 32; nt++) {
            // two independent 2-deep accumulator chains (halved HMMA latency chain)
            float c0a = 0.f, c1a = 0.f, c2a = 0.f, c3a = 0.f;
            float c0b = 0.f, c1b = 0.f, c2b = 0.f, c3b = 0.f;
            {
                uint32_t b00 = sBf[(nt * 4 + 0) * 64 + lane];
                uint32_t b01 = sBf[(nt * 4 + 0) * 64 + 32 + lane];
                uint32_t b10 = sBf[(nt * 4 + 1) * 64 + lane];
                uint32_t b11 = sBf[(nt * 4 + 1) * 64 + 32 + lane];
                uint32_t b20 = sBf[(nt * 4 + 2) * 64 + lane];
                uint32_t b21 = sBf[(nt * 4 + 2) * 64 + 32 + lane];
                uint32_t b30 = sBf[(nt * 4 + 3) * 64 + lane];
                uint32_t b31 = sBf[(nt * 4 + 3) * 64 + 32 + lane];
                mma16816(c0a, c1a, c2a, c3a, a[0][0], a[0][1], a[0][2], a[0][3], b00, b01);
                mma16816(c0b, c1b, c2b, c3b, a[1][0], a[1][1], a[1][2], a[1][3], b10, b11);
                mma16816(c0a, c1a, c2a, c3a, a[2][0], a[2][1], a[2][2], a[2][3], b20, b21);
                mma16816(c0b, c1b, c2b, c3b, a[3][0], a[3][1], a[3][2], a[3][3], b30, b31);
            }
            int col0 = nt * 8 + 2 * (lane & 3);
            float2 bv = *reinterpret_cast<const float2*>(sB1 + col0);
            float2 wv = *reinterpret_cast<const float2*>(sW2 + col0);
            ts0 = fmaf(fast_tanh((c0a + c0b) + bv.x), wv.x, ts0);
            ts0 = fmaf(fast_tanh((c1a + c1b) + bv.y), wv.y, ts0);
            ts1 = fmaf(fast_tanh((c2a + c2b) + bv.x), wv.x, ts1);
            ts1 = fmaf(fast_tanh((c3a + c3b) + bv.y), wv.y, ts1);
        }
        int node0 = tile * TILE_NODES + (rbase >> 1);
        int node1 = tile * TILE_NODES + ((rbase + 8) >> 1);
        wacc += (node0 < NN ? ts0 : 0.f) + (node1 < NN ? ts1 : 0.f);
    }

    wacc += __shfl_xor_sync(0xffffffffu, wacc, 1);
    wacc += __shfl_xor_sync(0xffffffffu, wacc, 2);
    __syncthreads();
    if ((lane & 3) == 0) atomicAdd(&sred[rbase & 1], wacc);
    __syncthreads();
    if (tid == 0) {
        atomicAdd(&g_w[0], sred[0]);
        atomicAdd(&g_w[1], sred[1]);
    }
}

// ---------------- final combine: out = b0*geo_mean + b1*trans --------------
__global__ void combine_kernel(float* __restrict__ out) {
    float w0 = g_w[0] * (1.f / NN);
    float w1 = g_w[1] * (1.f / NN);
    float m = fmaxf(w0, w1);
    float e0 = __expf(w0 - m), e1 = __expf(w1 - m);
    float inv = 1.f / (e0 + e1);
    float beta0 = e0 * inv, beta1 = e1 * inv;

    int idx = blockIdx.x * blockDim.x + threadIdx.x;
    if (idx >= NN * 16) return;
    int node = idx >> 4;
    int c = g_cnt[node];
    float invc = c > 0 ? 1.f / (float)c : 0.f;
    float4 g = reinterpret_cast<const float4*>(g_geo)[idx];
    float4 t = reinterpret_cast<const float4*>(g_trans)[idx];
    float4 o;
    o.x = beta0 * (g.x * invc) + beta1 * t.x;
    o.y = beta0 * (g.y * invc) + beta1 * t.y;
    o.z = beta0 * (g.z * invc) + beta1 * t.z;
    o.w = beta0 * (g.w * invc) + beta1 * t.w;
    reinterpret_cast<float4*>(out)[idx] = o;
}

// ---------------- launch ---------------------------------------------------
extern "C" void kernel_launch(void* const* d_in, const int* in_sizes, int n_in,
                              void* d_out, int out_size) {
    const float* loc = (const float*)d_in[0];
    const int* gs = (const int*)d_in[1];
    const int* gd = (const int*)d_in[2];
    const int* ts = (const int*)d_in[3];
    const int* td = (const int*)d_in[4];
    const float* tw = (const float*)d_in[5];
    const float* W1 = (const float*)d_in[6];
    const float* b1 = (const float*)d_in[7];
    const float* W2 = (const float*)d_in[8];
    int E = in_sizes[1];

    zero_kernel<<<256, 256>>>();
    convert_kernel<<<(NN * DD / 4 + 255) / 256, 256>>>((const float4*)loc);

    int eblk = (E + 255) / 256;
    fill_kernel<<<eblk, 256>>>(gs, gd, ts, td, tw, E);

    gather_kernel<<<(TT * 32 + 255) / 256, 256>>>();

    cudaFuncSetAttribute(semantic_mma_kernel,
                         cudaFuncAttributeMaxDynamicSharedMemorySize, SM_TOTAL);
    semantic_mma_kernel<<<592, 256, SM_TOTAL>>>(W1, b1, W2);

    combine_kernel<<<(NN * 16 + 255) / 256, 256>>>((float*)d_out);
}